// round 10
// baseline (speedup 1.0000x reference)
#include <cuda_runtime.h>
#include <cuda_bf16.h>
#include <cstdint>

// BilateralFilter (SqueezeSeg): out[b,z,a,k,c] = exp(-||x[b,z,a]-nbr_k||^2 / (2*theta_c^2))
// B=16, Z=64, A=512, K=14 (3x5 minus center), theta=[.015,.015,.01,.01]
// -> per (pixel,k) output float4 = (e1,e1,e2,e2), only 2 distinct exps.
//
// R9 resubmit (R9 bench died to container infra failure, no data produced).
// R6 schedule (TA=256 / 896 thr / ZC=8 / 256 CTAs, 1 barrier per z-step,
// prefetch depth 2, __stcs) with SoA smem tile:
//   float tx/ty/tz[4][264]; 264 % 32 = 8 -> circular rows sit at bank
//   offsets {0,8,16,24}; a warp's neighbor window spans <= 7 words/row, so
//   all LDS.32 are conflict-free single-phase (vs 2-way-conflicted LDS.128).

#define BB 16
#define ZZ 64
#define AA 512
#define KK 14

#define TA 256                // pixels (a) per CTA
#define NT 896                // threads
#define PT 4                  // outputs per thread per z-step
#define HW (TA + 4)           // 260 halo width
#define HWP 264               // padded row stride (HWP % 32 == 8)
#define ZC 8                  // z-rows per CTA

__global__ __launch_bounds__(NT, 2)
void bilateral_kernel(const float* __restrict__ x, float4* __restrict__ out)
{
    __shared__ float tx[4][HWP];   // circular rows, slot = z & 3
    __shared__ float ty[4][HWP];
    __shared__ float tz[4][HWP];

    const int tid = threadIdx.x;
    const int a0 = blockIdx.x * TA;
    const int z0 = blockIdx.y * ZC;
    const int b  = blockIdx.z;

    // ---- prologue: rows z0-1, z0, z0+1 into their slots ----
    for (int idx = tid; idx < 3 * HW; idx += NT) {
        const int r = idx / HW;
        const int c = idx - r * HW;
        const int gz = z0 + r - 1;
        const int ga = a0 + c - 2;
        float vx = 0.f, vy = 0.f, vz = 0.f;
        if (gz >= 0 && gz < ZZ && ga >= 0 && ga < AA) {
            const float* p = x + ((size_t)((b * ZZ + gz) * AA + ga)) * 3;
            vx = p[0]; vy = p[1]; vz = p[2];
        }
        const int s = gz & 3;
        tx[s][c] = vx; ty[s][c] = vy; tz[s][c] = vz;
    }

    // ---- decode once: k, (i,j) invariant for this thread ----
    const int p0 = tid / KK;          // 0..63
    const int k  = tid - p0 * KK;     // 0..13
    const int kk = k + (k >= 7);      // skip center (flat 7)
    const int i  = kk / 5;            // 0..2
    const int j  = kk - i * 5;        // 0..4

    // exp(-d2/(2 th^2)) = __expf(d2 * C), C = -1/(2 th^2)
    const float C1 = -1.0f / (2.0f * 0.015f * 0.015f);
    const float C2 = -1.0f / (2.0f * 0.01f  * 0.01f );

    float4* ob = out + ((size_t)((b * ZZ + z0) * AA + a0)) * KK + tid;

    // ---- initial register prefetch of row z0+2 ----
    const int ga_pf = a0 + tid - 2;
    const bool lane_pf = (tid < HW) && (ga_pf >= 0) && (ga_pf < AA);
    float px = 0.f, py = 0.f, pz = 0.f;
    {
        const int gz = z0 + 2;
        if (lane_pf && gz < ZZ) {
            const float* p = x + ((size_t)((b * ZZ + gz) * AA + ga_pf)) * 3;
            px = p[0]; py = p[1]; pz = p[2];
        }
    }

    #pragma unroll 1
    for (int z = z0; z < z0 + ZC; ++z) {
        __syncthreads();   // orders prior STS before this step's reads,
                           // and prior reads of slot (z+2)&3 before this STS

        // ---- STS prefetched row z+2 (slot disjoint from compute slots) ----
        if (tid < HW && z + 2 <= z0 + ZC) {
            const int s = (z + 2) & 3;
            tx[s][tid] = px; ty[s][tid] = py; tz[s][tid] = pz;
        }

        // ---- issue LDG prefetch for row z+3 (consumed next step) ----
        px = 0.f; py = 0.f; pz = 0.f;
        {
            const int gz = z + 3;
            if (lane_pf && gz < ZZ && z + 3 <= z0 + ZC) {
                const float* p = x + ((size_t)((b * ZZ + gz) * AA + ga_pf)) * 3;
                px = p[0]; py = p[1]; pz = p[2];
            }
        }

        // ---- compute row z (reads slots (z-1..z+1)&3 only) ----
        const int sc = z & 3;
        const int sn = (z - 1 + i) & 3;
        #pragma unroll
        for (int it = 0; it < PT; ++it) {
            const int p = p0 + it * 64;
            const float cx = tx[sc][p + 2];
            const float cy = ty[sc][p + 2];
            const float cz = tz[sc][p + 2];
            const float nx = tx[sn][p + j];
            const float ny = ty[sn][p + j];
            const float nz = tz[sn][p + j];
            const float dx = cx - nx;
            const float dy = cy - ny;
            const float dz = cz - nz;
            const float d2 = fmaf(dz, dz, fmaf(dy, dy, dx * dx));
            const float e1 = __expf(d2 * C1);
            const float e2 = __expf(d2 * C2);
            __stcs(&ob[it * NT], make_float4(e1, e1, e2, e2));
        }

        ob += (size_t)AA * KK;
    }
}

extern "C" void kernel_launch(void* const* d_in, const int* in_sizes, int n_in,
                              void* d_out, int out_size)
{
    (void)in_sizes; (void)n_in; (void)out_size;
    const float* x = (const float*)d_in[0];
    float4* out = (float4*)d_out;

    dim3 grid(AA / TA, ZZ / ZC, BB);   // 2 x 8 x 16 = 256 CTAs
    dim3 block(NT);                    // 896 threads
    bilateral_kernel<<<grid, block>>>(x, out);
}

// round 11
// speedup vs baseline: 1.0808x; 1.0808x over previous
#include <cuda_runtime.h>
#include <cuda_bf16.h>
#include <cstdint>

// BilateralFilter (SqueezeSeg): out[b,z,a,k,c] = exp(-||x[b,z,a]-nbr_k||^2 / (2*theta_c^2))
// B=16, Z=64, A=512, K=14 (3x5 minus center), theta=[.015,.015,.01,.01]
// -> per (pixel,k) output float4 = (e1,e1,e2,e2), only 2 distinct exps.
//
// R11: R6 base (AoS float4 tile, TA=256/896thr/occ2, __stcs, __expf) with
// double-row iterations: 8-slot circular buffer, each iteration computes
// rows z,z+1 (8 outputs/thread), STS rows z+3,z+4 (prefetched by two
// disjoint lane groups), LDGs rows z+5,z+6. 4 barriers/CTA instead of 8.

#define BB 16
#define ZZ 64
#define AA 512
#define KK 14

#define TA 256                // pixels (a) per CTA
#define NT 896                // threads
#define PT 4                  // outputs per thread per z-row
#define HW (TA + 4)           // 260 halo width
#define ZC 8                  // z-rows per CTA
#define ROWSTRIDE ((size_t)AA * KK)

__global__ __launch_bounds__(NT, 2)
void bilateral_kernel(const float* __restrict__ x, float4* __restrict__ out)
{
    __shared__ float4 tile[8][HW];   // circular rows, slot = gz & 7 (33,280 B)

    const int tid = threadIdx.x;
    const int a0 = blockIdx.x * TA;
    const int z0 = blockIdx.y * ZC;
    const int b  = blockIdx.z;

    // ---- prologue: rows z0-1 .. z0+2 into their slots ----
    for (int idx = tid; idx < 4 * HW; idx += NT) {
        const int r = idx / HW;
        const int c = idx - r * HW;
        const int gz = z0 + r - 1;
        const int ga = a0 + c - 2;
        float4 v = make_float4(0.f, 0.f, 0.f, 0.f);
        if (gz >= 0 && gz < ZZ && ga >= 0 && ga < AA) {
            const float* p = x + ((size_t)((b * ZZ + gz) * AA + ga)) * 3;
            v.x = p[0]; v.y = p[1]; v.z = p[2];
        }
        tile[gz & 7][c] = v;
    }

    // ---- decode once: k, (i,j) invariant for this thread ----
    const int p0 = tid / KK;          // 0..63
    const int k  = tid - p0 * KK;     // 0..13
    const int kk = k + (k >= 7);      // skip center (flat 7)
    const int i  = kk / 5;            // 0..2
    const int j  = kk - i * 5;        // 0..4

    const float C1 = -1.0f / (2.0f * 0.015f * 0.015f);
    const float C2 = -1.0f / (2.0f * 0.01f  * 0.01f );

    // ---- prefetch lane groups: A = lanes [0,HW) -> odd-offset rows (3,5,7),
    //      B = lanes [448,448+HW) -> even-offset rows (4,6,8) ----
    const bool gA = (tid < HW);
    const bool gB = (tid >= 448) && (tid < 448 + HW);
    const int  lc = gA ? tid : (tid - 448);       // halo column for this lane
    const int  ga_pf = a0 + lc - 2;
    const bool lane_ok = (gA || gB) && (ga_pf >= 0) && (ga_pf < AA);
    const int  offS = gA ? 3 : 4;                 // STS row offset base
    const int  offP = gA ? 5 : 6;                 // next-prefetch offset base

    float px = 0.f, py = 0.f, pz = 0.f;
    {   // initial prefetch: rows z0+3 (A), z0+4 (B)
        const int gz = z0 + offS;
        if (lane_ok && gz < ZZ) {
            const float* p = x + ((size_t)((b * ZZ + gz) * AA + ga_pf)) * 3;
            px = p[0]; py = p[1]; pz = p[2];
        }
    }

    float4* ob = out + ((size_t)((b * ZZ + z0) * AA + a0)) * KK + tid;

    #pragma unroll 1
    for (int t = 0; t < ZC / 2; ++t) {
        const int z = z0 + 2 * t;
        __syncthreads();   // orders prior STS before reads; prior reads
                           // of the overwritten slots before this STS

        // ---- STS prefetched rows z+3 (A) / z+4 (B); skip rows > z0+ZC ----
        if ((gA || gB) && (2 * t + offS) <= ZC)
            tile[(z + offS) & 7][lc] = make_float4(px, py, pz, 0.f);

        // ---- issue LDG prefetch rows z+5 (A) / z+6 (B) ----
        px = 0.f; py = 0.f; pz = 0.f;
        if (lane_ok && (2 * t + offP) <= ZC) {
            const int gz = z + offP;
            if (gz < ZZ) {
                const float* p = x + ((size_t)((b * ZZ + gz) * AA + ga_pf)) * 3;
                px = p[0]; py = p[1]; pz = p[2];
            }
        }

        // ---- compute rows z and z+1 (reads slots (z-1 .. z+2)&7 only) ----
        #pragma unroll
        for (int rr = 0; rr < 2; ++rr) {
            const int zz = z + rr;
            const int sc = zz & 7;
            const int sn = (zz - 1 + i) & 7;
            float4* obr = ob + (size_t)rr * ROWSTRIDE;
            #pragma unroll
            for (int it = 0; it < PT; ++it) {
                const int p = p0 + it * 64;
                const float4 c4 = tile[sc][p + 2];
                const float4 n4 = tile[sn][p + j];
                const float dx = c4.x - n4.x;
                const float dy = c4.y - n4.y;
                const float dz = c4.z - n4.z;
                const float d2 = fmaf(dz, dz, fmaf(dy, dy, dx * dx));
                const float e1 = __expf(d2 * C1);
                const float e2 = __expf(d2 * C2);
                __stcs(&obr[it * NT], make_float4(e1, e1, e2, e2));
            }
        }

        ob += 2 * ROWSTRIDE;
    }
}

extern "C" void kernel_launch(void* const* d_in, const int* in_sizes, int n_in,
                              void* d_out, int out_size)
{
    (void)in_sizes; (void)n_in; (void)out_size;
    const float* x = (const float*)d_in[0];
    float4* out = (float4*)d_out;

    dim3 grid(AA / TA, ZZ / ZC, BB);   // 2 x 8 x 16 = 256 CTAs
    dim3 block(NT);                    // 896 threads
    bilateral_kernel<<<grid, block>>>(x, out);
}